// round 7
// baseline (speedup 1.0000x reference)
#include <cuda_runtime.h>

#define D 256
#define H1 128
#define H2 64

// Folded weights: g_w[0..255] = class-0 column of W1@W2@W3, g_w[256..511] = class 1.
__device__ float g_w[2 * D];
__device__ float g_b[2];

// ---------------------------------------------------------------------------
// Fused fold (1 block x 1024 threads):
//   W23 = W2@W3 [128,2], tvec = b1@W2 + b2 [64]   (phase 1, warp-parallel jobs)
//   W_eff = W1@W23 [256,2], b_eff = tvec@W3 + b3  (phase 2, warp per row)
// Signals PDL completion as soon as g_w/g_b are globally visible.
// ---------------------------------------------------------------------------
__global__ void __launch_bounds__(1024)
fold_fused(const float* __restrict__ W1,
           const float* __restrict__ W2,
           const float* __restrict__ W3,
           const float* __restrict__ b1,
           const float* __restrict__ b2,
           const float* __restrict__ b3) {
    __shared__ float sW23c0[H1];
    __shared__ float sW23c1[H1];
    __shared__ float sTvec[H2];

    const int tid  = threadIdx.x;
    const int warp = tid >> 5;      // 0..31
    const int lane = tid & 31;

    // ---- Phase 1: 320 warp-parallel dot jobs over 32 warps (10 each) ----
#pragma unroll
    for (int i = 0; i < 10; ++i) {
        const int job = i * 32 + warp;
        float v;
        if (job < 256) {
            const int k = job >> 1;
            const int c = job & 1;
            const float* w2row = &W2[k * H2];
            v = fmaf(w2row[lane],      W3[lane * 2 + c],
                     w2row[lane + 32] * W3[(lane + 32) * 2 + c]);
        } else {
            const int j = job - 256;
            v =      b1[lane]      * W2[(lane)      * H2 + j];
            v = fmaf(b1[lane + 32],  W2[(lane + 32) * H2 + j], v);
            v = fmaf(b1[lane + 64],  W2[(lane + 64) * H2 + j], v);
            v = fmaf(b1[lane + 96],  W2[(lane + 96) * H2 + j], v);
        }
#pragma unroll
        for (int o = 16; o > 0; o >>= 1)
            v += __shfl_xor_sync(0xffffffffu, v, o);
        if (lane == 0) {
            if (job < 256) {
                const int k = job >> 1;
                if (job & 1) sW23c1[k] = v;
                else         sW23c0[k] = v;
            } else {
                sTvec[job - 256] = v + b2[job - 256];
            }
        }
    }
    __syncthreads();

    // ---- Phase 2: W_eff rows, one warp per row, 8 rows per warp ----
#pragma unroll
    for (int i = 0; i < 8; ++i) {
        const int row = i * 32 + warp;              // 0..255
        const float4 a  = *(const float4*)&W1[row * H1 + 4 * lane];
        const float4 c0 = *(const float4*)&sW23c0[4 * lane];
        const float4 c1 = *(const float4*)&sW23c1[4 * lane];

        float s0, s1;
        s0 = a.x * c0.x;            s1 = a.x * c1.x;
        s0 = fmaf(a.y, c0.y, s0);   s1 = fmaf(a.y, c1.y, s1);
        s0 = fmaf(a.z, c0.z, s0);   s1 = fmaf(a.z, c1.z, s1);
        s0 = fmaf(a.w, c0.w, s0);   s1 = fmaf(a.w, c1.w, s1);

#pragma unroll
        for (int o = 16; o > 0; o >>= 1) {
            s0 += __shfl_xor_sync(0xffffffffu, s0, o);
            s1 += __shfl_xor_sync(0xffffffffu, s1, o);
        }
        if (lane == 0) {
            g_w[row]     = s0;
            g_w[D + row] = s1;
        }
    }

    // ---- Bias fold: warp 0 ----
    if (warp == 0) {
        float t0 = sTvec[lane], t1 = sTvec[lane + 32];
        float bb0 = fmaf(t0, W3[lane * 2 + 0], t1 * W3[(lane + 32) * 2 + 0]);
        float bb1 = fmaf(t0, W3[lane * 2 + 1], t1 * W3[(lane + 32) * 2 + 1]);
#pragma unroll
        for (int o = 16; o > 0; o >>= 1) {
            bb0 += __shfl_xor_sync(0xffffffffu, bb0, o);
            bb1 += __shfl_xor_sync(0xffffffffu, bb1, o);
        }
        if (lane == 0) {
            g_b[0] = bb0 + b3[0];
            g_b[1] = bb1 + b3[1];
        }
    }

    // ---- PDL: make g_w/g_b visible, then release the dependent grid ----
    __syncthreads();
    __threadfence();
    asm volatile("griddepcontrol.launch_dependents;");
}

// ---------------------------------------------------------------------------
// Main kernel: one warp per edge, grid-stride over edges.
// Launched with PDL; waits on the fold only right before reading g_w.
// Bound at ~93% of the measured ~6300 B/cyc LTS cap.
// ---------------------------------------------------------------------------
__global__ void __launch_bounds__(256)
edge_predict_kernel(const float* __restrict__ h,
                    const int* __restrict__ edges,   // int32 indices
                    float* __restrict__ out, int E) {
    const int lane   = threadIdx.x & 31;
    const int warp   = (blockIdx.x * blockDim.x + threadIdx.x) >> 5;
    const int nwarps = (gridDim.x * blockDim.x) >> 5;

    // Wait for the fold's results (PDL); preamble above overlaps with fold.
    asm volatile("griddepcontrol.wait;" ::: "memory");

    // Per-lane folded weights, register-resident across all edges.
    const float4 w0a = *(const float4*)&g_w[4 * lane];
    const float4 w0b = *(const float4*)&g_w[128 + 4 * lane];
    const float4 w1a = *(const float4*)&g_w[D + 4 * lane];
    const float4 w1b = *(const float4*)&g_w[D + 128 + 4 * lane];
    const float bias0 = g_b[0];
    const float bias1 = g_b[1];

    for (int e = warp; e < E; e += nwarps) {
        const int2 st = __ldg((const int2*)edges + e);
        const long long s = st.x;
        const long long t = st.y;

        const float4* hs = (const float4*)h + s * (D / 4);
        const float4* ht = (const float4*)h + t * (D / 4);

        const float4 x0 = __ldg(hs + lane);
        const float4 y0 = __ldg(ht + lane);
        const float4 x1 = __ldg(hs + lane + 32);
        const float4 y1 = __ldg(ht + lane + 32);

        float p, a0, a1;
        p = x0.x * y0.x; a0 = p * w0a.x;          a1 = p * w1a.x;
        p = x0.y * y0.y; a0 = fmaf(p, w0a.y, a0); a1 = fmaf(p, w1a.y, a1);
        p = x0.z * y0.z; a0 = fmaf(p, w0a.z, a0); a1 = fmaf(p, w1a.z, a1);
        p = x0.w * y0.w; a0 = fmaf(p, w0a.w, a0); a1 = fmaf(p, w1a.w, a1);
        p = x1.x * y1.x; a0 = fmaf(p, w0b.x, a0); a1 = fmaf(p, w1b.x, a1);
        p = x1.y * y1.y; a0 = fmaf(p, w0b.y, a0); a1 = fmaf(p, w1b.y, a1);
        p = x1.z * y1.z; a0 = fmaf(p, w0b.z, a0); a1 = fmaf(p, w1b.z, a1);
        p = x1.w * y1.w; a0 = fmaf(p, w0b.w, a0); a1 = fmaf(p, w1b.w, a1);

#pragma unroll
        for (int o = 16; o > 0; o >>= 1) {
            a0 += __shfl_xor_sync(0xffffffffu, a0, o);
            a1 += __shfl_xor_sync(0xffffffffu, a1, o);
        }

        if (lane == 0) {
            a0 += bias0;
            a1 += bias1;
            float m  = fmaxf(a0, a1);
            float e0 = expf(a0 - m);
            float e1 = expf(a1 - m);
            float inv = 1.0f / (e0 + e1);
            ((float2*)out)[e] = make_float2(e0 * inv, e1 * inv);
        }
    }
}

extern "C" void kernel_launch(void* const* d_in, const int* in_sizes, int n_in,
                              void* d_out, int out_size) {
    const float* h     = (const float*)d_in[0];
    const int*   edges = (const int*)d_in[1];
    const float* W1    = (const float*)d_in[2];
    const float* b1    = (const float*)d_in[3];
    const float* W2    = (const float*)d_in[4];
    const float* b2    = (const float*)d_in[5];
    const float* W3    = (const float*)d_in[6];
    const float* b3    = (const float*)d_in[7];
    float*       out   = (float*)d_out;

    const int E = in_sizes[1] / 2;

    fold_fused<<<1, 1024>>>(W1, W2, W3, b1, b2, b3);

    // Main kernel with PDL: allowed to launch while fold_fused is running;
    // it gates itself on griddepcontrol.wait before reading g_w.
    cudaLaunchConfig_t cfg = {};
    cfg.gridDim  = dim3(2048, 1, 1);
    cfg.blockDim = dim3(256, 1, 1);
    cfg.dynamicSmemBytes = 0;
    cfg.stream = 0;  // legacy default stream (matches capture behavior)
    cudaLaunchAttribute attr[1];
    attr[0].id = cudaLaunchAttributeProgrammaticStreamSerialization;
    attr[0].val.programmaticStreamSerializationAllowed = 1;
    cfg.attrs = attr;
    cfg.numAttrs = 1;
    cudaLaunchKernelEx(&cfg, edge_predict_kernel, h, edges, out, E);
}

// round 8
// speedup vs baseline: 1.1541x; 1.1541x over previous
#include <cuda_runtime.h>

#define D 256
#define H1 128
#define H2 64

// Folded weights: g_w[0..255] = class-0 column of W1@W2@W3, g_w[256..511] = class 1.
__device__ float g_w[2 * D];
__device__ float g_b[2];

// ---------------------------------------------------------------------------
// Fused fold (1 block x 1024 threads):
//   W23 = W2@W3 [128,2], tvec = b1@W2 + b2 [64]   (phase 1, warp-parallel jobs)
//   W_eff = W1@W23 [256,2], b_eff = tvec@W3 + b3  (phase 2, warp per row)
// ---------------------------------------------------------------------------
__global__ void __launch_bounds__(1024)
fold_fused(const float* __restrict__ W1,
           const float* __restrict__ W2,
           const float* __restrict__ W3,
           const float* __restrict__ b1,
           const float* __restrict__ b2,
           const float* __restrict__ b3) {
    __shared__ float sW23c0[H1];
    __shared__ float sW23c1[H1];
    __shared__ float sTvec[H2];

    const int tid  = threadIdx.x;
    const int warp = tid >> 5;      // 0..31
    const int lane = tid & 31;

    // ---- Phase 1: 320 warp-parallel dot jobs over 32 warps (10 each) ----
#pragma unroll
    for (int i = 0; i < 10; ++i) {
        const int job = i * 32 + warp;
        float v;
        if (job < 256) {
            const int k = job >> 1;
            const int c = job & 1;
            const float* w2row = &W2[k * H2];
            v = fmaf(w2row[lane],      W3[lane * 2 + c],
                     w2row[lane + 32] * W3[(lane + 32) * 2 + c]);
        } else {
            const int j = job - 256;
            v =      b1[lane]      * W2[(lane)      * H2 + j];
            v = fmaf(b1[lane + 32],  W2[(lane + 32) * H2 + j], v);
            v = fmaf(b1[lane + 64],  W2[(lane + 64) * H2 + j], v);
            v = fmaf(b1[lane + 96],  W2[(lane + 96) * H2 + j], v);
        }
#pragma unroll
        for (int o = 16; o > 0; o >>= 1)
            v += __shfl_xor_sync(0xffffffffu, v, o);
        if (lane == 0) {
            if (job < 256) {
                const int k = job >> 1;
                if (job & 1) sW23c1[k] = v;
                else         sW23c0[k] = v;
            } else {
                sTvec[job - 256] = v + b2[job - 256];
            }
        }
    }
    __syncthreads();

    // ---- Phase 2: W_eff rows, one warp per row, 8 rows per warp ----
#pragma unroll
    for (int i = 0; i < 8; ++i) {
        const int row = i * 32 + warp;              // 0..255
        const float4 a  = *(const float4*)&W1[row * H1 + 4 * lane];
        const float4 c0 = *(const float4*)&sW23c0[4 * lane];
        const float4 c1 = *(const float4*)&sW23c1[4 * lane];

        float s0, s1;
        s0 = a.x * c0.x;            s1 = a.x * c1.x;
        s0 = fmaf(a.y, c0.y, s0);   s1 = fmaf(a.y, c1.y, s1);
        s0 = fmaf(a.z, c0.z, s0);   s1 = fmaf(a.z, c1.z, s1);
        s0 = fmaf(a.w, c0.w, s0);   s1 = fmaf(a.w, c1.w, s1);

#pragma unroll
        for (int o = 16; o > 0; o >>= 1) {
            s0 += __shfl_xor_sync(0xffffffffu, s0, o);
            s1 += __shfl_xor_sync(0xffffffffu, s1, o);
        }
        if (lane == 0) {
            g_w[row]     = s0;
            g_w[D + row] = s1;
        }
    }

    // ---- Bias fold: warp 0 ----
    if (warp == 0) {
        float t0 = sTvec[lane], t1 = sTvec[lane + 32];
        float bb0 = fmaf(t0, W3[lane * 2 + 0], t1 * W3[(lane + 32) * 2 + 0]);
        float bb1 = fmaf(t0, W3[lane * 2 + 1], t1 * W3[(lane + 32) * 2 + 1]);
#pragma unroll
        for (int o = 16; o > 0; o >>= 1) {
            bb0 += __shfl_xor_sync(0xffffffffu, bb0, o);
            bb1 += __shfl_xor_sync(0xffffffffu, bb1, o);
        }
        if (lane == 0) {
            g_b[0] = bb0 + b3[0];
            g_b[1] = bb1 + b3[1];
        }
    }
}

// ---------------------------------------------------------------------------
// Main kernel: one warp per edge, grid-stride over edges.
// Grid sized to 8880 = 148 SMs x 60 (multiple of both 5- and 6-CTA/SM
// residency quanta) so wave quantization tail is ~0 regardless of achieved
// occupancy. Per-warp work drops to ~14 edges.
// ---------------------------------------------------------------------------
__global__ void __launch_bounds__(256)
edge_predict_kernel(const float* __restrict__ h,
                    const int* __restrict__ edges,   // int32 indices
                    float* __restrict__ out, int E) {
    const int lane   = threadIdx.x & 31;
    const int warp   = (blockIdx.x * blockDim.x + threadIdx.x) >> 5;
    const int nwarps = (gridDim.x * blockDim.x) >> 5;

    // Per-lane folded weights, register-resident across all edges.
    const float4 w0a = *(const float4*)&g_w[4 * lane];
    const float4 w0b = *(const float4*)&g_w[128 + 4 * lane];
    const float4 w1a = *(const float4*)&g_w[D + 4 * lane];
    const float4 w1b = *(const float4*)&g_w[D + 128 + 4 * lane];
    const float bias0 = g_b[0];
    const float bias1 = g_b[1];

    for (int e = warp; e < E; e += nwarps) {
        const int2 st = __ldg((const int2*)edges + e);
        const long long s = st.x;
        const long long t = st.y;

        const float4* hs = (const float4*)h + s * (D / 4);
        const float4* ht = (const float4*)h + t * (D / 4);

        const float4 x0 = __ldg(hs + lane);
        const float4 y0 = __ldg(ht + lane);
        const float4 x1 = __ldg(hs + lane + 32);
        const float4 y1 = __ldg(ht + lane + 32);

        float p, a0, a1;
        p = x0.x * y0.x; a0 = p * w0a.x;          a1 = p * w1a.x;
        p = x0.y * y0.y; a0 = fmaf(p, w0a.y, a0); a1 = fmaf(p, w1a.y, a1);
        p = x0.z * y0.z; a0 = fmaf(p, w0a.z, a0); a1 = fmaf(p, w1a.z, a1);
        p = x0.w * y0.w; a0 = fmaf(p, w0a.w, a0); a1 = fmaf(p, w1a.w, a1);
        p = x1.x * y1.x; a0 = fmaf(p, w0b.x, a0); a1 = fmaf(p, w1b.x, a1);
        p = x1.y * y1.y; a0 = fmaf(p, w0b.y, a0); a1 = fmaf(p, w1b.y, a1);
        p = x1.z * y1.z; a0 = fmaf(p, w0b.z, a0); a1 = fmaf(p, w1b.z, a1);
        p = x1.w * y1.w; a0 = fmaf(p, w0b.w, a0); a1 = fmaf(p, w1b.w, a1);

#pragma unroll
        for (int o = 16; o > 0; o >>= 1) {
            a0 += __shfl_xor_sync(0xffffffffu, a0, o);
            a1 += __shfl_xor_sync(0xffffffffu, a1, o);
        }

        if (lane == 0) {
            a0 += bias0;
            a1 += bias1;
            float m  = fmaxf(a0, a1);
            float e0 = expf(a0 - m);
            float e1 = expf(a1 - m);
            float inv = 1.0f / (e0 + e1);
            ((float2*)out)[e] = make_float2(e0 * inv, e1 * inv);
        }
    }
}

extern "C" void kernel_launch(void* const* d_in, const int* in_sizes, int n_in,
                              void* d_out, int out_size) {
    const float* h     = (const float*)d_in[0];
    const int*   edges = (const int*)d_in[1];
    const float* W1    = (const float*)d_in[2];
    const float* b1    = (const float*)d_in[3];
    const float* W2    = (const float*)d_in[4];
    const float* b2    = (const float*)d_in[5];
    const float* W3    = (const float*)d_in[6];
    const float* b3    = (const float*)d_in[7];
    float*       out   = (float*)d_out;

    const int E = in_sizes[1] / 2;

    fold_fused<<<1, 1024>>>(W1, W2, W3, b1, b2, b3);
    // 8880 = 148 x 60: integer number of waves at 5 or 6 resident CTAs/SM.
    edge_predict_kernel<<<8880, 256>>>(h, edges, out, E);
}